// round 1
// baseline (speedup 1.0000x reference)
#include <cuda_runtime.h>
#include <stdint.h>

#define HH 1024
#define WW 1024
#define BB 8
#define NPIX (HH*WW)          // 1048576
#define NPAIR 16              // 2 images x 8 batches, pair = img*8 + b
#define H1BINS 1056
#define H2BINS 4096
#define H3BINS 256

// 64MB scratch for gA, gB (device globals are allowed; allocation APIs are not)
__device__ float g_scr[2][BB][NPIX];
__device__ unsigned int g_hist1[NPAIR][H1BINS];
__device__ unsigned int g_hist2[NPAIR][H2BINS];
__device__ unsigned int g_hist3[NPAIR][H3BINS];
__device__ double g_loss;
__device__ unsigned int g_sel1[NPAIR];
__device__ unsigned int g_sel2[NPAIR];
__device__ unsigned int g_krem[NPAIR];
__device__ float g_kth[NPAIR];

// ---------------------------------------------------------------------------
// K0: zero all accumulators/histograms (graph replays must be deterministic)
// ---------------------------------------------------------------------------
__global__ void k_zero() {
    int idx = blockIdx.x * blockDim.x + threadIdx.x;
    int stride = gridDim.x * blockDim.x;
    const int n1 = NPAIR * H1BINS;
    const int n2 = NPAIR * H2BINS;
    const int n3 = NPAIR * H3BINS;
    const int tot = n1 + n2 + n3;
    unsigned int* h1 = &g_hist1[0][0];
    unsigned int* h2 = &g_hist2[0][0];
    unsigned int* h3 = &g_hist3[0][0];
    for (int i = idx; i < tot; i += stride) {
        if (i < n1) h1[i] = 0;
        else if (i < n1 + n2) h2[i - n1] = 0;
        else h3[i - n1 - n2] = 0;
    }
    if (idx == 0) g_loss = 0.0;
}

// ---------------------------------------------------------------------------
// Sobel at (y,x) of a [HH][WW] plane, zero padding. XLA conv is cross-corr;
// both kernels are (anti)symmetric so |.| is flip-invariant anyway.
// ---------------------------------------------------------------------------
__device__ __forceinline__ float sobel_at(const float* __restrict__ img, int y, int x) {
    float v00 = 0.f, v01 = 0.f, v02 = 0.f;
    float v10 = 0.f, v12 = 0.f;
    float v20 = 0.f, v21 = 0.f, v22 = 0.f;
    const bool ym = (y > 0), yp = (y < HH - 1);
    const bool xm = (x > 0), xp = (x < WW - 1);
    const float* r0 = img + (size_t)(y - 1) * WW;
    const float* r1 = img + (size_t)y * WW;
    const float* r2 = img + (size_t)(y + 1) * WW;
    if (ym) {
        if (xm) v00 = __ldg(r0 + x - 1);
        v01 = __ldg(r0 + x);
        if (xp) v02 = __ldg(r0 + x + 1);
    }
    if (xm) v10 = __ldg(r1 + x - 1);
    if (xp) v12 = __ldg(r1 + x + 1);
    if (yp) {
        if (xm) v20 = __ldg(r2 + x - 1);
        v21 = __ldg(r2 + x);
        if (xp) v22 = __ldg(r2 + x + 1);
    }
    float gx = (v02 - v00) + 2.f * (v12 - v10) + (v22 - v20);
    float gy = (v00 - v20) + 2.f * (v01 - v21) + (v02 - v22);
    return fabsf(gx) + fabsf(gy);
}

// ---------------------------------------------------------------------------
// K1: fused sobel(A,B,F) + store gA,gB + loss partial + top-12-bit histograms
// grid (NPIX/256, BB), 256 threads
// ---------------------------------------------------------------------------
__global__ void k_sobel(const float* __restrict__ A,
                        const float* __restrict__ Bi,
                        const float* __restrict__ F) {
    __shared__ unsigned int shA[H1BINS];
    __shared__ unsigned int shB[H1BINS];
    __shared__ float wsum[8];

    const int b = blockIdx.y;
    const int tid = threadIdx.x;
    for (int i = tid; i < H1BINS; i += 256) { shA[i] = 0u; shB[i] = 0u; }
    __syncthreads();

    const int idx = blockIdx.x * 256 + tid;     // pixel index in plane
    const int y = idx >> 10;
    const int x = idx & 1023;
    const size_t plane = (size_t)b * 3 * NPIX;  // channel 0 of batch b

    float ga = sobel_at(A + plane, y, x);
    float gb = sobel_at(Bi + plane, y, x);
    float gf = sobel_at(F + plane, y, x);

    g_scr[0][b][idx] = ga;
    g_scr[1][b][idx] = gb;

    float diff = fabsf(gf - fmaxf(ga, gb));

    unsigned int ua = __float_as_uint(ga);
    unsigned int ub = __float_as_uint(gb);
    atomicAdd(&shA[min(ua >> 20, (unsigned)(H1BINS - 1))], 1u);
    atomicAdd(&shB[min(ub >> 20, (unsigned)(H1BINS - 1))], 1u);

    // block reduce diff
    float s = diff;
    #pragma unroll
    for (int o = 16; o > 0; o >>= 1) s += __shfl_down_sync(0xffffffffu, s, o);
    if ((tid & 31) == 0) wsum[tid >> 5] = s;
    __syncthreads();
    if (tid < 8) {
        float t = wsum[tid];
        #pragma unroll
        for (int o = 4; o > 0; o >>= 1) t += __shfl_down_sync(0xffu, t, o);
        if (tid == 0) atomicAdd(&g_loss, (double)t);
    }

    for (int i = tid; i < H1BINS; i += 256) {
        unsigned int ca = shA[i], cb = shB[i];
        if (ca) atomicAdd(&g_hist1[b][i], ca);
        if (cb) atomicAdd(&g_hist1[BB + b][i], cb);
    }
}

// ---------------------------------------------------------------------------
// Scan kernels (tiny): one thread per (image,batch) pair
// ---------------------------------------------------------------------------
__global__ void k_scan1(const int* __restrict__ thr) {
    int p = threadIdx.x;
    if (p >= NPAIR) return;
    unsigned int k = (unsigned int)thr[0];
    unsigned long long cum = 0;
    for (int bin = 0; bin < H1BINS; bin++) {
        unsigned int c = g_hist1[p][bin];
        if (cum + c >= (unsigned long long)k) {
            g_sel1[p] = (unsigned int)bin;
            g_krem[p] = k - (unsigned int)cum;
            return;
        }
        cum += c;
    }
}

__global__ void k_scan2() {
    int p = threadIdx.x;
    if (p >= NPAIR) return;
    unsigned int k = g_krem[p];
    unsigned int cum = 0;
    for (int bin = 0; bin < H2BINS; bin++) {
        unsigned int c = g_hist2[p][bin];
        if (cum + c >= k) {
            g_sel2[p] = (unsigned int)bin;
            g_krem[p] = k - cum;
            return;
        }
        cum += c;
    }
}

__global__ void k_scan3() {
    int p = threadIdx.x;
    if (p >= NPAIR) return;
    unsigned int k = g_krem[p];
    unsigned int cum = 0;
    for (int bin = 0; bin < H3BINS; bin++) {
        unsigned int c = g_hist3[p][bin];
        if (cum + c >= k) {
            unsigned int kbits = (g_sel1[p] << 20) | (g_sel2[p] << 8) | (unsigned int)bin;
            g_kth[p] = __uint_as_float(kbits);
            return;
        }
        cum += c;
    }
}

// ---------------------------------------------------------------------------
// K3: histogram bits[19:8] of values matching sel1. grid (NPIX/1024, BB, 2)
// ---------------------------------------------------------------------------
__global__ void k_hist2() {
    __shared__ unsigned int sh[H2BINS];
    const int img = blockIdx.z, b = blockIdx.y;
    const int p = img * BB + b;
    const unsigned int sel1 = g_sel1[p];
    for (int i = threadIdx.x; i < H2BINS; i += 256) sh[i] = 0u;
    __syncthreads();

    const float4* __restrict__ src = (const float4*)g_scr[img][b];
    float4 v = src[blockIdx.x * 256 + threadIdx.x];
    const float vv[4] = {v.x, v.y, v.z, v.w};
    #pragma unroll
    for (int j = 0; j < 4; j++) {
        unsigned int u = __float_as_uint(vv[j]);
        if ((u >> 20) == sel1) atomicAdd(&sh[(u >> 8) & 0xFFFu], 1u);
    }
    __syncthreads();
    for (int i = threadIdx.x; i < H2BINS; i += 256) {
        unsigned int c = sh[i];
        if (c) atomicAdd(&g_hist2[p][i], c);
    }
}

// ---------------------------------------------------------------------------
// K5: histogram bits[7:0] of values matching (sel1,sel2). grid (NPIX/1024, BB, 2)
// ---------------------------------------------------------------------------
__global__ void k_hist3() {
    __shared__ unsigned int sh[H3BINS];
    const int img = blockIdx.z, b = blockIdx.y;
    const int p = img * BB + b;
    const unsigned int prefix = (g_sel1[p] << 12) | g_sel2[p];
    for (int i = threadIdx.x; i < H3BINS; i += 256) sh[i] = 0u;
    __syncthreads();

    const float4* __restrict__ src = (const float4*)g_scr[img][b];
    float4 v = src[blockIdx.x * 256 + threadIdx.x];
    const float vv[4] = {v.x, v.y, v.z, v.w};
    #pragma unroll
    for (int j = 0; j < 4; j++) {
        unsigned int u = __float_as_uint(vv[j]);
        if ((u >> 8) == prefix) atomicAdd(&sh[u & 0xFFu], 1u);
    }
    __syncthreads();
    for (int i = threadIdx.x; i < H3BINS; i += 256) {
        unsigned int c = sh[i];
        if (c) atomicAdd(&g_hist3[p][i], c);
    }
}

// ---------------------------------------------------------------------------
// K6: write masks + loss. out layout: [loss, maskA(8*1M), maskB(8*1M)]
// grid (NPIX/256, BB, 2), 256 threads (scalar stores: out+1 breaks alignment)
// ---------------------------------------------------------------------------
__global__ void k_mask(float* __restrict__ out) {
    const int img = blockIdx.z, b = blockIdx.y;
    const float kth = g_kth[img * BB + b];
    const int i = blockIdx.x * 256 + threadIdx.x;
    float v = g_scr[img][b][i];
    size_t off = 1 + (size_t)img * BB * NPIX + (size_t)b * NPIX + i;
    out[off] = (v >= kth) ? 1.0f : 0.0f;
    if (img == 0 && b == 0 && blockIdx.x == 0 && threadIdx.x == 0) {
        out[0] = (float)(g_loss / (double)((size_t)BB * NPIX));
    }
}

// ---------------------------------------------------------------------------
extern "C" void kernel_launch(void* const* d_in, const int* in_sizes, int n_in,
                              void* d_out, int out_size) {
    const float* A  = (const float*)d_in[0];
    const float* Bi = (const float*)d_in[1];
    const float* F  = (const float*)d_in[2];
    const int*   thr = (const int*)d_in[3];
    float* out = (float*)d_out;

    k_zero<<<128, 256>>>();
    k_sobel<<<dim3(NPIX / 256, BB), 256>>>(A, Bi, F);
    k_scan1<<<1, 32>>>(thr);
    k_hist2<<<dim3(NPIX / 1024, BB, 2), 256>>>();
    k_scan2<<<1, 32>>>();
    k_hist3<<<dim3(NPIX / 1024, BB, 2), 256>>>();
    k_scan3<<<1, 32>>>();
    k_mask<<<dim3(NPIX / 256, BB, 2), 256>>>(out);
}

// round 3
// speedup vs baseline: 1.4005x; 1.4005x over previous
#include <cuda_runtime.h>
#include <stdint.h>

#define HH 1024
#define WW 1024
#define BB 8
#define NPIX (HH*WW)          // 1048576
#define NPAIR 16              // pair = img*8 + b
#define H1BINS 1056
#define H2BINS 4096
#define H3BINS 256
#define VPB 2048              // float4 vectors per block in k_sobel (8192 px)
#define SOBEL_ITERS 8

__device__ float g_scr[2][BB][NPIX];           // gA, gB (64 MB)
__device__ unsigned int g_hist1[NPAIR][H1BINS];
__device__ unsigned int g_hist2[NPAIR][H2BINS];
__device__ unsigned int g_hist3[NPAIR][H3BINS];
__device__ double g_loss;
__device__ unsigned int g_sel1[NPAIR];
__device__ unsigned int g_sel2[NPAIR];
__device__ unsigned int g_krem[NPAIR];
__device__ float g_kth[NPAIR];

// ---------------------------------------------------------------------------
// K0: zero accumulators (graph replays must be deterministic)
// ---------------------------------------------------------------------------
__global__ void k_zero() {
    int idx = blockIdx.x * blockDim.x + threadIdx.x;
    int stride = gridDim.x * blockDim.x;
    const int n1 = NPAIR * H1BINS;
    const int n2 = NPAIR * H2BINS;
    const int n3 = NPAIR * H3BINS;
    const int tot = n1 + n2 + n3;
    unsigned int* h1 = &g_hist1[0][0];
    unsigned int* h2 = &g_hist2[0][0];
    unsigned int* h3 = &g_hist3[0][0];
    for (int i = idx; i < tot; i += stride) {
        if (i < n1) h1[i] = 0;
        else if (i < n1 + n2) h2[i - n1] = 0;
        else h3[i - n1 - n2] = 0;
    }
    if (idx == 0) g_loss = 0.0;
}

// ---------------------------------------------------------------------------
// 6-wide row fetch: floats x-1..x+4 for the 4 pixels starting at x = 4*vx
// ---------------------------------------------------------------------------
__device__ __forceinline__ void load_row6(const float* __restrict__ img,
                                          int y, int vx, float* v) {
    const float* row = img + ((size_t)y << 10);
    float4 c = __ldg((const float4*)row + vx);
    v[0] = (vx > 0) ? __ldg(row + (vx << 2) - 1) : 0.f;
    v[1] = c.x; v[2] = c.y; v[3] = c.z; v[4] = c.w;
    v[5] = (vx < (WW / 4 - 1)) ? __ldg(row + (vx << 2) + 4) : 0.f;
}

// Sobel |Gx|+|Gy| for 4 consecutive pixels (zero padding at borders)
__device__ __forceinline__ float4 sobel4v(const float* __restrict__ img,
                                          int y, int vx) {
    float t[6], m[6], bo[6];
    if (y > 0) {
        load_row6(img, y - 1, vx, t);
    } else {
        for (int i = 0; i < 6; i++) t[i] = 0.f;
    }
    load_row6(img, y, vx, m);
    if (y < HH - 1) {
        load_row6(img, y + 1, vx, bo);
    } else {
        for (int i = 0; i < 6; i++) bo[i] = 0.f;
    }
    float g[4];
    #pragma unroll
    for (int i = 0; i < 4; i++) {
        float gx = (t[i + 2] - t[i]) + 2.f * (m[i + 2] - m[i]) + (bo[i + 2] - bo[i]);
        float gy = (t[i] - bo[i]) + 2.f * (t[i + 1] - bo[i + 1]) + (t[i + 2] - bo[i + 2]);
        g[i] = fabsf(gx) + fabsf(gy);
    }
    return make_float4(g[0], g[1], g[2], g[3]);
}

// ---------------------------------------------------------------------------
// K1: fused sobel(A,B,F) + scratch store + loss + top-12-bit histograms
// grid (128, BB), 256 threads, 8 float4 iterations per thread
// ---------------------------------------------------------------------------
__global__ void k_sobel(const float* __restrict__ A,
                        const float* __restrict__ Bi,
                        const float* __restrict__ F) {
    __shared__ unsigned int shA[H1BINS];
    __shared__ unsigned int shB[H1BINS];
    __shared__ float wsum[8];

    const int b = blockIdx.y;
    const int tid = threadIdx.x;
    for (int i = tid; i < H1BINS; i += 256) { shA[i] = 0u; shB[i] = 0u; }
    __syncthreads();

    const size_t plane = (size_t)b * 3 * NPIX;  // channel 0 of batch b
    const float* pa = A + plane;
    const float* pb = Bi + plane;
    const float* pf = F + plane;
    float4* outA = (float4*)g_scr[0][b];
    float4* outB = (float4*)g_scr[1][b];

    float lsum = 0.f;
    #pragma unroll
    for (int j = 0; j < SOBEL_ITERS; j++) {
        const int vec = blockIdx.x * VPB + j * 256 + tid;
        const int y = vec >> 8;     // 256 float4 per row
        const int vx = vec & 255;

        float4 ga = sobel4v(pa, y, vx);
        float4 gb = sobel4v(pb, y, vx);
        float4 gf = sobel4v(pf, y, vx);

        outA[vec] = ga;
        outB[vec] = gb;

        lsum += fabsf(gf.x - fmaxf(ga.x, gb.x));
        lsum += fabsf(gf.y - fmaxf(ga.y, gb.y));
        lsum += fabsf(gf.z - fmaxf(ga.z, gb.z));
        lsum += fabsf(gf.w - fmaxf(ga.w, gb.w));

        atomicAdd(&shA[min(__float_as_uint(ga.x) >> 20, (unsigned)(H1BINS - 1))], 1u);
        atomicAdd(&shA[min(__float_as_uint(ga.y) >> 20, (unsigned)(H1BINS - 1))], 1u);
        atomicAdd(&shA[min(__float_as_uint(ga.z) >> 20, (unsigned)(H1BINS - 1))], 1u);
        atomicAdd(&shA[min(__float_as_uint(ga.w) >> 20, (unsigned)(H1BINS - 1))], 1u);
        atomicAdd(&shB[min(__float_as_uint(gb.x) >> 20, (unsigned)(H1BINS - 1))], 1u);
        atomicAdd(&shB[min(__float_as_uint(gb.y) >> 20, (unsigned)(H1BINS - 1))], 1u);
        atomicAdd(&shB[min(__float_as_uint(gb.z) >> 20, (unsigned)(H1BINS - 1))], 1u);
        atomicAdd(&shB[min(__float_as_uint(gb.w) >> 20, (unsigned)(H1BINS - 1))], 1u);
    }

    // block-reduce loss
    float s = lsum;
    #pragma unroll
    for (int o = 16; o > 0; o >>= 1) s += __shfl_down_sync(0xffffffffu, s, o);
    if ((tid & 31) == 0) wsum[tid >> 5] = s;
    __syncthreads();
    if (tid < 8) {
        float t2 = wsum[tid];
        #pragma unroll
        for (int o = 4; o > 0; o >>= 1) t2 += __shfl_down_sync(0xffu, t2, o);
        if (tid == 0) atomicAdd(&g_loss, (double)t2);
    }

    __syncthreads();
    for (int i = tid; i < H1BINS; i += 256) {
        unsigned int ca = shA[i], cb = shB[i];
        if (ca) atomicAdd(&g_hist1[b][i], ca);
        if (cb) atomicAdd(&g_hist1[BB + b][i], cb);
    }
}

// ---------------------------------------------------------------------------
// Scan kernels (tiny): one thread per (image,batch) pair
// ---------------------------------------------------------------------------
__global__ void k_scan1(const int* __restrict__ thr) {
    int p = threadIdx.x;
    if (p >= NPAIR) return;
    unsigned int k = (unsigned int)thr[0];
    unsigned long long cum = 0;
    for (int bin = 0; bin < H1BINS; bin++) {
        unsigned int c = g_hist1[p][bin];
        if (cum + c >= (unsigned long long)k) {
            g_sel1[p] = (unsigned int)bin;
            g_krem[p] = k - (unsigned int)cum;
            return;
        }
        cum += c;
    }
}

__global__ void k_scan2() {
    int p = threadIdx.x;
    if (p >= NPAIR) return;
    unsigned int k = g_krem[p];
    unsigned int cum = 0;
    for (int bin = 0; bin < H2BINS; bin++) {
        unsigned int c = g_hist2[p][bin];
        if (cum + c >= k) {
            g_sel2[p] = (unsigned int)bin;
            g_krem[p] = k - cum;
            return;
        }
        cum += c;
    }
}

__global__ void k_scan3() {
    int p = threadIdx.x;
    if (p >= NPAIR) return;
    unsigned int k = g_krem[p];
    unsigned int cum = 0;
    for (int bin = 0; bin < H3BINS; bin++) {
        unsigned int c = g_hist3[p][bin];
        if (cum + c >= k) {
            unsigned int kbits = (g_sel1[p] << 20) | (g_sel2[p] << 8) | (unsigned int)bin;
            g_kth[p] = __uint_as_float(kbits);
            return;
        }
        cum += c;
    }
}

// ---------------------------------------------------------------------------
// K3: streaming hist of bits[19:8] for values matching sel1.
// Matches are rare -> direct global atomics, no shared hist overhead.
// ---------------------------------------------------------------------------
__global__ void k_hist2() {
    const float4* __restrict__ src = (const float4*)&g_scr[0][0][0];
    const unsigned total = NPAIR * (NPIX / 4);          // 4M float4
    const unsigned stride = gridDim.x * blockDim.x;
    for (unsigned i = blockIdx.x * blockDim.x + threadIdx.x; i < total; i += stride) {
        const unsigned p = i >> 18;                     // 262144 vec per plane
        const unsigned sel = g_sel1[p];
        float4 v = src[i];
        unsigned u;
        u = __float_as_uint(v.x); if ((u >> 20) == sel) atomicAdd(&g_hist2[p][(u >> 8) & 0xFFFu], 1u);
        u = __float_as_uint(v.y); if ((u >> 20) == sel) atomicAdd(&g_hist2[p][(u >> 8) & 0xFFFu], 1u);
        u = __float_as_uint(v.z); if ((u >> 20) == sel) atomicAdd(&g_hist2[p][(u >> 8) & 0xFFFu], 1u);
        u = __float_as_uint(v.w); if ((u >> 20) == sel) atomicAdd(&g_hist2[p][(u >> 8) & 0xFFFu], 1u);
    }
}

// ---------------------------------------------------------------------------
// K5: streaming hist of bits[7:0] for values matching (sel1,sel2)
// ---------------------------------------------------------------------------
__global__ void k_hist3() {
    const float4* __restrict__ src = (const float4*)&g_scr[0][0][0];
    const unsigned total = NPAIR * (NPIX / 4);
    const unsigned stride = gridDim.x * blockDim.x;
    for (unsigned i = blockIdx.x * blockDim.x + threadIdx.x; i < total; i += stride) {
        const unsigned p = i >> 18;
        const unsigned pref = (g_sel1[p] << 12) | g_sel2[p];
        float4 v = src[i];
        unsigned u;
        u = __float_as_uint(v.x); if ((u >> 8) == pref) atomicAdd(&g_hist3[p][u & 0xFFu], 1u);
        u = __float_as_uint(v.y); if ((u >> 8) == pref) atomicAdd(&g_hist3[p][u & 0xFFu], 1u);
        u = __float_as_uint(v.z); if ((u >> 8) == pref) atomicAdd(&g_hist3[p][u & 0xFFu], 1u);
        u = __float_as_uint(v.w); if ((u >> 8) == pref) atomicAdd(&g_hist3[p][u & 0xFFu], 1u);
    }
}

// ---------------------------------------------------------------------------
// K6: masks + loss. out layout: [loss, maskA(8*1M), maskB(8*1M)]
// (out+1 offset breaks 16B alignment -> 4 coalesced scalar stores per thread)
// ---------------------------------------------------------------------------
__global__ void k_mask(float* __restrict__ out) {
    const float4* __restrict__ src = (const float4*)&g_scr[0][0][0];
    const unsigned i = blockIdx.x * blockDim.x + threadIdx.x;  // one vec each
    const unsigned p = i >> 18;
    const float kth = g_kth[p];
    float4 v = src[i];
    size_t off = 1 + ((size_t)i << 2);
    out[off + 0] = (v.x >= kth) ? 1.0f : 0.0f;
    out[off + 1] = (v.y >= kth) ? 1.0f : 0.0f;
    out[off + 2] = (v.z >= kth) ? 1.0f : 0.0f;
    out[off + 3] = (v.w >= kth) ? 1.0f : 0.0f;
    if (i == 0) out[0] = (float)(g_loss / 8388608.0);
}

// ---------------------------------------------------------------------------
extern "C" void kernel_launch(void* const* d_in, const int* in_sizes, int n_in,
                              void* d_out, int out_size) {
    const float* A   = (const float*)d_in[0];
    const float* Bi  = (const float*)d_in[1];
    const float* F   = (const float*)d_in[2];
    const int*   thr = (const int*)d_in[3];
    float* out = (float*)d_out;

    k_zero<<<64, 256>>>();
    k_sobel<<<dim3(NPIX / 4 / VPB, BB), 256>>>(A, Bi, F);   // (128, 8)
    k_scan1<<<1, 32>>>(thr);
    k_hist2<<<2048, 256>>>();
    k_scan2<<<1, 32>>>();
    k_hist3<<<2048, 256>>>();
    k_scan3<<<1, 32>>>();
    k_mask<<<NPAIR * (NPIX / 4) / 256, 256>>>(out);         // 16384 blocks
}

// round 4
// speedup vs baseline: 3.9479x; 2.8190x over previous
#include <cuda_runtime.h>
#include <stdint.h>

#define HH 1024
#define WW 1024
#define BB 8
#define NPIX (HH*WW)          // 1048576
#define NPAIR 16              // pair = img*8 + b
#define H1BINS 1056
#define H2BINS 4096
#define H3BINS 256
#define SROWS 16              // rows per sobel block

__device__ float g_scr[2][BB][NPIX];           // gA, gB (64 MB)
__device__ unsigned int g_hist1[NPAIR][H1BINS];
__device__ unsigned int g_hist2[NPAIR][H2BINS];
__device__ unsigned int g_hist3[NPAIR][H3BINS];
__device__ double g_loss;
__device__ unsigned int g_sel1[NPAIR];
__device__ unsigned int g_sel2[NPAIR];
__device__ unsigned int g_krem[NPAIR];
__device__ float g_kth[NPAIR];

// ---------------------------------------------------------------------------
// K0: zero accumulators (graph replays must be deterministic)
// ---------------------------------------------------------------------------
__global__ void k_zero() {
    int idx = blockIdx.x * blockDim.x + threadIdx.x;
    int stride = gridDim.x * blockDim.x;
    const int n1 = NPAIR * H1BINS;
    const int n2 = NPAIR * H2BINS;
    const int n3 = NPAIR * H3BINS;
    const int tot = n1 + n2 + n3;
    unsigned int* h1 = &g_hist1[0][0];
    unsigned int* h2 = &g_hist2[0][0];
    unsigned int* h3 = &g_hist3[0][0];
    for (int i = idx; i < tot; i += stride) {
        if (i < n1) h1[i] = 0;
        else if (i < n1 + n2) h2[i - n1] = 0;
        else h3[i - n1 - n2] = 0;
    }
    if (idx == 0) g_loss = 0.0;
}

// ---------------------------------------------------------------------------
// Row fetch: floats x-1..x+4 for the 4 pixels at x = 4*vx (zero at borders)
// ---------------------------------------------------------------------------
__device__ __forceinline__ void load_row6(const float* __restrict__ img,
                                          int y, int vx, float* v) {
    const float* row = img + ((size_t)y << 10);
    float4 c = __ldg((const float4*)row + vx);
    v[0] = (vx > 0) ? __ldg(row + (vx << 2) - 1) : 0.f;
    v[1] = c.x; v[2] = c.y; v[3] = c.z; v[4] = c.w;
    v[5] = (vx < (WW / 4 - 1)) ? __ldg(row + (vx << 2) + 4) : 0.f;
}

__device__ __forceinline__ float4 sobel_rows(const float* t, const float* m,
                                             const float* bo) {
    float g[4];
    #pragma unroll
    for (int i = 0; i < 4; i++) {
        float gx = (t[i + 2] - t[i]) + 2.f * (m[i + 2] - m[i]) + (bo[i + 2] - bo[i]);
        float gy = (t[i] - bo[i]) + 2.f * (t[i + 1] - bo[i + 1]) + (t[i + 2] - bo[i + 2]);
        g[i] = fabsf(gx) + fabsf(gy);
    }
    return make_float4(g[0], g[1], g[2], g[3]);
}

// ---------------------------------------------------------------------------
// K1: fused sobel(A,B,F), row-sliding strip. grid (HH/SROWS, BB), 256 thr.
// Thread = one float4 column; keeps 3 rows x 3 images in registers.
// ---------------------------------------------------------------------------
__global__ void k_sobel(const float* __restrict__ A,
                        const float* __restrict__ Bi,
                        const float* __restrict__ F) {
    __shared__ unsigned int shA[H1BINS];
    __shared__ unsigned int shB[H1BINS];
    __shared__ float wsum[8];

    const int b = blockIdx.y;
    const int tid = threadIdx.x;               // vx = float4 column
    for (int i = tid; i < H1BINS; i += 256) { shA[i] = 0u; shB[i] = 0u; }
    __syncthreads();

    const size_t plane = (size_t)b * 3 * NPIX;
    const float* pa = A + plane;
    const float* pb = Bi + plane;
    const float* pf = F + plane;
    float4* outA = (float4*)g_scr[0][b];
    float4* outB = (float4*)g_scr[1][b];

    const int y0 = blockIdx.x * SROWS;

    float ta[6], ma[6], tb[6], mb[6], tf[6], mf[6];
    if (y0 > 0) {
        load_row6(pa, y0 - 1, tid, ta);
        load_row6(pb, y0 - 1, tid, tb);
        load_row6(pf, y0 - 1, tid, tf);
    } else {
        #pragma unroll
        for (int i = 0; i < 6; i++) { ta[i] = 0.f; tb[i] = 0.f; tf[i] = 0.f; }
    }
    load_row6(pa, y0, tid, ma);
    load_row6(pb, y0, tid, mb);
    load_row6(pf, y0, tid, mf);

    float lsum = 0.f;
    #pragma unroll 2
    for (int y = y0; y < y0 + SROWS; y++) {
        float ba[6], bb[6], bf[6];
        if (y + 1 < HH) {
            load_row6(pa, y + 1, tid, ba);
            load_row6(pb, y + 1, tid, bb);
            load_row6(pf, y + 1, tid, bf);
        } else {
            #pragma unroll
            for (int i = 0; i < 6; i++) { ba[i] = 0.f; bb[i] = 0.f; bf[i] = 0.f; }
        }

        float4 ga = sobel_rows(ta, ma, ba);
        float4 gb = sobel_rows(tb, mb, bb);
        float4 gf = sobel_rows(tf, mf, bf);

        const int vec = (y << 8) + tid;
        outA[vec] = ga;
        outB[vec] = gb;

        lsum += fabsf(gf.x - fmaxf(ga.x, gb.x));
        lsum += fabsf(gf.y - fmaxf(ga.y, gb.y));
        lsum += fabsf(gf.z - fmaxf(ga.z, gb.z));
        lsum += fabsf(gf.w - fmaxf(ga.w, gb.w));

        atomicAdd(&shA[min(__float_as_uint(ga.x) >> 20, (unsigned)(H1BINS - 1))], 1u);
        atomicAdd(&shA[min(__float_as_uint(ga.y) >> 20, (unsigned)(H1BINS - 1))], 1u);
        atomicAdd(&shA[min(__float_as_uint(ga.z) >> 20, (unsigned)(H1BINS - 1))], 1u);
        atomicAdd(&shA[min(__float_as_uint(ga.w) >> 20, (unsigned)(H1BINS - 1))], 1u);
        atomicAdd(&shB[min(__float_as_uint(gb.x) >> 20, (unsigned)(H1BINS - 1))], 1u);
        atomicAdd(&shB[min(__float_as_uint(gb.y) >> 20, (unsigned)(H1BINS - 1))], 1u);
        atomicAdd(&shB[min(__float_as_uint(gb.z) >> 20, (unsigned)(H1BINS - 1))], 1u);
        atomicAdd(&shB[min(__float_as_uint(gb.w) >> 20, (unsigned)(H1BINS - 1))], 1u);

        #pragma unroll
        for (int i = 0; i < 6; i++) {
            ta[i] = ma[i]; ma[i] = ba[i];
            tb[i] = mb[i]; mb[i] = bb[i];
            tf[i] = mf[i]; mf[i] = bf[i];
        }
    }

    // block-reduce loss
    float s = lsum;
    #pragma unroll
    for (int o = 16; o > 0; o >>= 1) s += __shfl_down_sync(0xffffffffu, s, o);
    if ((tid & 31) == 0) wsum[tid >> 5] = s;
    __syncthreads();
    if (tid < 8) {
        float t2 = wsum[tid];
        #pragma unroll
        for (int o = 4; o > 0; o >>= 1) t2 += __shfl_down_sync(0xffu, t2, o);
        if (tid == 0) atomicAdd(&g_loss, (double)t2);
    }

    __syncthreads();
    for (int i = tid; i < H1BINS; i += 256) {
        unsigned int ca = shA[i], cb = shB[i];
        if (ca) atomicAdd(&g_hist1[b][i], ca);
        if (cb) atomicAdd(&g_hist1[BB + b][i], cb);
    }
}

// ---------------------------------------------------------------------------
// Block-wide exclusive scan (blockDim multiple of 32, <=1024)
// ---------------------------------------------------------------------------
__device__ __forceinline__ unsigned block_excl_scan(unsigned local,
                                                    unsigned* warp_sh) {
    const int lane = threadIdx.x & 31;
    const int wid = threadIdx.x >> 5;
    const int nwarps = blockDim.x >> 5;
    unsigned v = local;
    #pragma unroll
    for (int o = 1; o < 32; o <<= 1) {
        unsigned n = __shfl_up_sync(0xffffffffu, v, o);
        if (lane >= o) v += n;
    }
    if (lane == 31) warp_sh[wid] = v;
    __syncthreads();
    if (wid == 0) {
        unsigned w = (lane < nwarps) ? warp_sh[lane] : 0u;
        #pragma unroll
        for (int o = 1; o < 32; o <<= 1) {
            unsigned n = __shfl_up_sync(0xffffffffu, w, o);
            if (lane >= o) w += n;
        }
        if (lane < nwarps) warp_sh[lane] = w;
    }
    __syncthreads();
    unsigned base = (wid > 0) ? warp_sh[wid - 1] : 0u;
    return base + v - local;   // exclusive prefix
}

// ---------------------------------------------------------------------------
// Parallel k-crossing scans: one block per pair, 4 contiguous bins/thread
// ---------------------------------------------------------------------------
__global__ void k_scan1(const int* __restrict__ thr) {
    __shared__ unsigned ws[32];
    const int p = blockIdx.x;
    const int tid = threadIdx.x;
    const unsigned k = (unsigned)thr[0];
    unsigned bins[4] = {0u, 0u, 0u, 0u};
    const int base = tid * 4;
    if (base < H1BINS) {
        uint4 v = *(const uint4*)&g_hist1[p][base];
        bins[0] = v.x; bins[1] = v.y; bins[2] = v.z; bins[3] = v.w;
    }
    unsigned local = bins[0] + bins[1] + bins[2] + bins[3];
    unsigned cum = block_excl_scan(local, ws);
    #pragma unroll
    for (int j = 0; j < 4; j++) {
        unsigned nb = cum + bins[j];
        if (cum < k && nb >= k) { g_sel1[p] = base + j; g_krem[p] = k - cum; }
        cum = nb;
    }
}

__global__ void k_scan2() {
    __shared__ unsigned ws[32];
    const int p = blockIdx.x;
    const int tid = threadIdx.x;
    const unsigned k = g_krem[p];
    __syncthreads();
    const int base = tid * 4;
    uint4 v = *(const uint4*)&g_hist2[p][base];
    unsigned bins[4] = {v.x, v.y, v.z, v.w};
    unsigned local = bins[0] + bins[1] + bins[2] + bins[3];
    unsigned cum = block_excl_scan(local, ws);
    #pragma unroll
    for (int j = 0; j < 4; j++) {
        unsigned nb = cum + bins[j];
        if (cum < k && nb >= k) { g_sel2[p] = base + j; g_krem[p] = k - cum; }
        cum = nb;
    }
}

__global__ void k_scan3() {
    __shared__ unsigned ws[32];
    const int p = blockIdx.x;
    const int tid = threadIdx.x;
    const unsigned k = g_krem[p];
    const int base = tid * 4;
    uint4 v = *(const uint4*)&g_hist3[p][base];
    unsigned bins[4] = {v.x, v.y, v.z, v.w};
    unsigned local = bins[0] + bins[1] + bins[2] + bins[3];
    unsigned cum = block_excl_scan(local, ws);
    #pragma unroll
    for (int j = 0; j < 4; j++) {
        unsigned nb = cum + bins[j];
        if (cum < k && nb >= k) {
            unsigned kbits = (g_sel1[p] << 20) | (g_sel2[p] << 8) | (unsigned)(base + j);
            g_kth[p] = __uint_as_float(kbits);
        }
        cum = nb;
    }
}

// ---------------------------------------------------------------------------
// K3: streaming hist of bits[19:8] for values matching sel1.
// 8 independent loads in flight per thread (MLP).
// ---------------------------------------------------------------------------
__global__ void k_hist2() {
    const float4* __restrict__ src = (const float4*)&g_scr[0][0][0];
    const unsigned idx = blockIdx.x * 256 + threadIdx.x;
    const unsigned stride = 2048u * 256u;   // grid*block
    float4 v[8];
    #pragma unroll
    for (int j = 0; j < 8; j++) v[j] = src[idx + j * stride];
    #pragma unroll
    for (int j = 0; j < 8; j++) {
        const unsigned p = (idx + j * stride) >> 18;
        const unsigned sel = g_sel1[p];
        unsigned u;
        u = __float_as_uint(v[j].x); if ((u >> 20) == sel) atomicAdd(&g_hist2[p][(u >> 8) & 0xFFFu], 1u);
        u = __float_as_uint(v[j].y); if ((u >> 20) == sel) atomicAdd(&g_hist2[p][(u >> 8) & 0xFFFu], 1u);
        u = __float_as_uint(v[j].z); if ((u >> 20) == sel) atomicAdd(&g_hist2[p][(u >> 8) & 0xFFFu], 1u);
        u = __float_as_uint(v[j].w); if ((u >> 20) == sel) atomicAdd(&g_hist2[p][(u >> 8) & 0xFFFu], 1u);
    }
}

__global__ void k_hist3() {
    const float4* __restrict__ src = (const float4*)&g_scr[0][0][0];
    const unsigned idx = blockIdx.x * 256 + threadIdx.x;
    const unsigned stride = 2048u * 256u;
    float4 v[8];
    #pragma unroll
    for (int j = 0; j < 8; j++) v[j] = src[idx + j * stride];
    #pragma unroll
    for (int j = 0; j < 8; j++) {
        const unsigned p = (idx + j * stride) >> 18;
        const unsigned pref = (g_sel1[p] << 12) | g_sel2[p];
        unsigned u;
        u = __float_as_uint(v[j].x); if ((u >> 8) == pref) atomicAdd(&g_hist3[p][u & 0xFFu], 1u);
        u = __float_as_uint(v[j].y); if ((u >> 8) == pref) atomicAdd(&g_hist3[p][u & 0xFFu], 1u);
        u = __float_as_uint(v[j].z); if ((u >> 8) == pref) atomicAdd(&g_hist3[p][u & 0xFFu], 1u);
        u = __float_as_uint(v[j].w); if ((u >> 8) == pref) atomicAdd(&g_hist3[p][u & 0xFFu], 1u);
    }
}

// ---------------------------------------------------------------------------
// K6: masks + loss. out layout: [loss, maskA(8*1M), maskB(8*1M)]
// ---------------------------------------------------------------------------
__global__ void k_mask(float* __restrict__ out) {
    const float4* __restrict__ src = (const float4*)&g_scr[0][0][0];
    const unsigned i = blockIdx.x * blockDim.x + threadIdx.x;
    const unsigned p = i >> 18;
    const float kth = g_kth[p];
    float4 v = src[i];
    size_t off = 1 + ((size_t)i << 2);
    out[off + 0] = (v.x >= kth) ? 1.0f : 0.0f;
    out[off + 1] = (v.y >= kth) ? 1.0f : 0.0f;
    out[off + 2] = (v.z >= kth) ? 1.0f : 0.0f;
    out[off + 3] = (v.w >= kth) ? 1.0f : 0.0f;
    if (i == 0) out[0] = (float)(g_loss / 8388608.0);
}

// ---------------------------------------------------------------------------
extern "C" void kernel_launch(void* const* d_in, const int* in_sizes, int n_in,
                              void* d_out, int out_size) {
    const float* A   = (const float*)d_in[0];
    const float* Bi  = (const float*)d_in[1];
    const float* F   = (const float*)d_in[2];
    const int*   thr = (const int*)d_in[3];
    float* out = (float*)d_out;

    k_zero<<<64, 256>>>();
    k_sobel<<<dim3(HH / SROWS, BB), 256>>>(A, Bi, F);   // (64, 8)
    k_scan1<<<NPAIR, 512>>>(thr);
    k_hist2<<<2048, 256>>>();
    k_scan2<<<NPAIR, 1024>>>();
    k_hist3<<<2048, 256>>>();
    k_scan3<<<NPAIR, 64>>>();
    k_mask<<<NPAIR * (NPIX / 4) / 256, 256>>>(out);     // 16384 blocks
}

// round 5
// speedup vs baseline: 4.2300x; 1.0715x over previous
#include <cuda_runtime.h>
#include <stdint.h>

#define HH 1024
#define WW 1024
#define BB 8
#define NPIX (HH*WW)          // 1048576
#define NPAIR 16              // pair = img*8 + b
#define H1BINS 1056
#define H2BINS 4096
#define H3BINS 256
#define SROWS 16              // rows per sobel block

__device__ float g_scr[2][BB][NPIX];           // gA, gB (64 MB) -> L2 resident
__device__ unsigned int g_hist1[NPAIR][H1BINS];
__device__ unsigned int g_hist2[NPAIR][H2BINS];
__device__ unsigned int g_hist3[NPAIR][H3BINS];
__device__ double g_loss;
__device__ unsigned int g_sel1[NPAIR];
__device__ unsigned int g_sel2[NPAIR];
__device__ unsigned int g_krem[NPAIR];
__device__ float g_kth[NPAIR];

// ---------------------------------------------------------------------------
// K0: zero accumulators (graph replays must be deterministic)
// ---------------------------------------------------------------------------
__global__ void k_zero() {
    int idx = blockIdx.x * blockDim.x + threadIdx.x;
    int stride = gridDim.x * blockDim.x;
    const int n1 = NPAIR * H1BINS;
    const int n2 = NPAIR * H2BINS;
    const int n3 = NPAIR * H3BINS;
    const int tot = n1 + n2 + n3;
    unsigned int* h1 = &g_hist1[0][0];
    unsigned int* h2 = &g_hist2[0][0];
    unsigned int* h3 = &g_hist3[0][0];
    for (int i = idx; i < tot; i += stride) {
        if (i < n1) h1[i] = 0;
        else if (i < n1 + n2) h2[i - n1] = 0;
        else h3[i - n1 - n2] = 0;
    }
    if (idx == 0) g_loss = 0.0;
}

// ---------------------------------------------------------------------------
// Row fetch (streaming, evict-first: keep input OUT of L2 so scratch stays)
// floats x-1..x+4 for the 4 pixels at x = 4*vx, zero at borders
// ---------------------------------------------------------------------------
__device__ __forceinline__ void load_row6(const float* __restrict__ img,
                                          int y, int vx, float* v) {
    const float* row = img + ((size_t)y << 10);
    float4 c = __ldcs((const float4*)row + vx);
    v[0] = (vx > 0) ? __ldcs(row + (vx << 2) - 1) : 0.f;
    v[1] = c.x; v[2] = c.y; v[3] = c.z; v[4] = c.w;
    v[5] = (vx < (WW / 4 - 1)) ? __ldcs(row + (vx << 2) + 4) : 0.f;
}

__device__ __forceinline__ float4 sobel_rows(const float* t, const float* m,
                                             const float* bo) {
    float g[4];
    #pragma unroll
    for (int i = 0; i < 4; i++) {
        float gx = (t[i + 2] - t[i]) + 2.f * (m[i + 2] - m[i]) + (bo[i + 2] - bo[i]);
        float gy = (t[i] - bo[i]) + 2.f * (t[i + 1] - bo[i + 1]) + (t[i + 2] - bo[i + 2]);
        g[i] = fabsf(gx) + fabsf(gy);
    }
    return make_float4(g[0], g[1], g[2], g[3]);
}

// ---------------------------------------------------------------------------
// K1: fused sobel(A,B,F), row-sliding strip. grid (HH/SROWS, BB), 256 thr.
// ---------------------------------------------------------------------------
__global__ void k_sobel(const float* __restrict__ A,
                        const float* __restrict__ Bi,
                        const float* __restrict__ F) {
    __shared__ unsigned int shA[H1BINS];
    __shared__ unsigned int shB[H1BINS];
    __shared__ float wsum[8];

    const int b = blockIdx.y;
    const int tid = threadIdx.x;               // vx = float4 column
    for (int i = tid; i < H1BINS; i += 256) { shA[i] = 0u; shB[i] = 0u; }
    __syncthreads();

    const size_t plane = (size_t)b * 3 * NPIX;
    const float* pa = A + plane;
    const float* pb = Bi + plane;
    const float* pf = F + plane;
    float4* outA = (float4*)g_scr[0][b];
    float4* outB = (float4*)g_scr[1][b];

    const int y0 = blockIdx.x * SROWS;

    float ta[6], ma[6], tb[6], mb[6], tf[6], mf[6];
    if (y0 > 0) {
        load_row6(pa, y0 - 1, tid, ta);
        load_row6(pb, y0 - 1, tid, tb);
        load_row6(pf, y0 - 1, tid, tf);
    } else {
        #pragma unroll
        for (int i = 0; i < 6; i++) { ta[i] = 0.f; tb[i] = 0.f; tf[i] = 0.f; }
    }
    load_row6(pa, y0, tid, ma);
    load_row6(pb, y0, tid, mb);
    load_row6(pf, y0, tid, mf);

    float lsum = 0.f;
    #pragma unroll 2
    for (int y = y0; y < y0 + SROWS; y++) {
        float ba[6], bb[6], bf[6];
        if (y + 1 < HH) {
            load_row6(pa, y + 1, tid, ba);
            load_row6(pb, y + 1, tid, bb);
            load_row6(pf, y + 1, tid, bf);
        } else {
            #pragma unroll
            for (int i = 0; i < 6; i++) { ba[i] = 0.f; bb[i] = 0.f; bf[i] = 0.f; }
        }

        float4 ga = sobel_rows(ta, ma, ba);
        float4 gb = sobel_rows(tb, mb, bb);
        float4 gf = sobel_rows(tf, mf, bf);

        const int vec = (y << 8) + tid;
        outA[vec] = ga;
        outB[vec] = gb;

        lsum += fabsf(gf.x - fmaxf(ga.x, gb.x));
        lsum += fabsf(gf.y - fmaxf(ga.y, gb.y));
        lsum += fabsf(gf.z - fmaxf(ga.z, gb.z));
        lsum += fabsf(gf.w - fmaxf(ga.w, gb.w));

        atomicAdd(&shA[min(__float_as_uint(ga.x) >> 20, (unsigned)(H1BINS - 1))], 1u);
        atomicAdd(&shA[min(__float_as_uint(ga.y) >> 20, (unsigned)(H1BINS - 1))], 1u);
        atomicAdd(&shA[min(__float_as_uint(ga.z) >> 20, (unsigned)(H1BINS - 1))], 1u);
        atomicAdd(&shA[min(__float_as_uint(ga.w) >> 20, (unsigned)(H1BINS - 1))], 1u);
        atomicAdd(&shB[min(__float_as_uint(gb.x) >> 20, (unsigned)(H1BINS - 1))], 1u);
        atomicAdd(&shB[min(__float_as_uint(gb.y) >> 20, (unsigned)(H1BINS - 1))], 1u);
        atomicAdd(&shB[min(__float_as_uint(gb.z) >> 20, (unsigned)(H1BINS - 1))], 1u);
        atomicAdd(&shB[min(__float_as_uint(gb.w) >> 20, (unsigned)(H1BINS - 1))], 1u);

        #pragma unroll
        for (int i = 0; i < 6; i++) {
            ta[i] = ma[i]; ma[i] = ba[i];
            tb[i] = mb[i]; mb[i] = bb[i];
            tf[i] = mf[i]; mf[i] = bf[i];
        }
    }

    // block-reduce loss
    float s = lsum;
    #pragma unroll
    for (int o = 16; o > 0; o >>= 1) s += __shfl_down_sync(0xffffffffu, s, o);
    if ((tid & 31) == 0) wsum[tid >> 5] = s;
    __syncthreads();
    if (tid < 8) {
        float t2 = wsum[tid];
        #pragma unroll
        for (int o = 4; o > 0; o >>= 1) t2 += __shfl_down_sync(0xffu, t2, o);
        if (tid == 0) atomicAdd(&g_loss, (double)t2);
    }

    __syncthreads();
    for (int i = tid; i < H1BINS; i += 256) {
        unsigned int ca = shA[i], cb = shB[i];
        if (ca) atomicAdd(&g_hist1[b][i], ca);
        if (cb) atomicAdd(&g_hist1[BB + b][i], cb);
    }
}

// ---------------------------------------------------------------------------
// Block-wide exclusive scan (blockDim multiple of 32, <=1024)
// ---------------------------------------------------------------------------
__device__ __forceinline__ unsigned block_excl_scan(unsigned local,
                                                    unsigned* warp_sh) {
    const int lane = threadIdx.x & 31;
    const int wid = threadIdx.x >> 5;
    const int nwarps = blockDim.x >> 5;
    unsigned v = local;
    #pragma unroll
    for (int o = 1; o < 32; o <<= 1) {
        unsigned n = __shfl_up_sync(0xffffffffu, v, o);
        if (lane >= o) v += n;
    }
    if (lane == 31) warp_sh[wid] = v;
    __syncthreads();
    if (wid == 0) {
        unsigned w = (lane < nwarps) ? warp_sh[lane] : 0u;
        #pragma unroll
        for (int o = 1; o < 32; o <<= 1) {
            unsigned n = __shfl_up_sync(0xffffffffu, w, o);
            if (lane >= o) w += n;
        }
        if (lane < nwarps) warp_sh[lane] = w;
    }
    __syncthreads();
    unsigned base = (wid > 0) ? warp_sh[wid - 1] : 0u;
    return base + v - local;   // exclusive prefix
}

// ---------------------------------------------------------------------------
// Parallel k-crossing scans: one block per pair, 4 contiguous bins/thread
// ---------------------------------------------------------------------------
__global__ void k_scan1(const int* __restrict__ thr) {
    __shared__ unsigned ws[32];
    const int p = blockIdx.x;
    const int tid = threadIdx.x;
    const unsigned k = (unsigned)thr[0];
    unsigned bins[4] = {0u, 0u, 0u, 0u};
    const int base = tid * 4;
    if (base < H1BINS) {
        uint4 v = *(const uint4*)&g_hist1[p][base];
        bins[0] = v.x; bins[1] = v.y; bins[2] = v.z; bins[3] = v.w;
    }
    unsigned local = bins[0] + bins[1] + bins[2] + bins[3];
    unsigned cum = block_excl_scan(local, ws);
    #pragma unroll
    for (int j = 0; j < 4; j++) {
        unsigned nb = cum + bins[j];
        if (cum < k && nb >= k) { g_sel1[p] = base + j; g_krem[p] = k - cum; }
        cum = nb;
    }
}

__global__ void k_scan2() {
    __shared__ unsigned ws[32];
    const int p = blockIdx.x;
    const int tid = threadIdx.x;
    const unsigned k = g_krem[p];
    __syncthreads();
    const int base = tid * 4;
    uint4 v = *(const uint4*)&g_hist2[p][base];
    unsigned bins[4] = {v.x, v.y, v.z, v.w};
    unsigned local = bins[0] + bins[1] + bins[2] + bins[3];
    unsigned cum = block_excl_scan(local, ws);
    #pragma unroll
    for (int j = 0; j < 4; j++) {
        unsigned nb = cum + bins[j];
        if (cum < k && nb >= k) { g_sel2[p] = base + j; g_krem[p] = k - cum; }
        cum = nb;
    }
}

__global__ void k_scan3() {
    __shared__ unsigned ws[32];
    const int p = blockIdx.x;
    const int tid = threadIdx.x;
    const unsigned k = g_krem[p];
    const int base = tid * 4;
    uint4 v = *(const uint4*)&g_hist3[p][base];
    unsigned bins[4] = {v.x, v.y, v.z, v.w};
    unsigned local = bins[0] + bins[1] + bins[2] + bins[3];
    unsigned cum = block_excl_scan(local, ws);
    #pragma unroll
    for (int j = 0; j < 4; j++) {
        unsigned nb = cum + bins[j];
        if (cum < k && nb >= k) {
            unsigned kbits = (g_sel1[p] << 20) | (g_sel2[p] << 8) | (unsigned)(base + j);
            g_kth[p] = __uint_as_float(kbits);
        }
        cum = nb;
    }
}

// ---------------------------------------------------------------------------
// K3: streaming hist of bits[19:8] for values matching sel1.
// 4 independent loads per thread, 4096 blocks (higher occupancy than 8x).
// Reads should hit L2 (scratch resident).
// ---------------------------------------------------------------------------
__global__ void __launch_bounds__(256) k_hist2() {
    const float4* __restrict__ src = (const float4*)&g_scr[0][0][0];
    const unsigned idx = blockIdx.x * 256 + threadIdx.x;
    const unsigned stride = 4096u * 256u;   // 1M threads, 4 vec each
    float4 v[4];
    #pragma unroll
    for (int j = 0; j < 4; j++) v[j] = src[idx + j * stride];
    #pragma unroll
    for (int j = 0; j < 4; j++) {
        const unsigned p = (idx + j * stride) >> 18;
        const unsigned sel = g_sel1[p];
        unsigned u;
        u = __float_as_uint(v[j].x); if ((u >> 20) == sel) atomicAdd(&g_hist2[p][(u >> 8) & 0xFFFu], 1u);
        u = __float_as_uint(v[j].y); if ((u >> 20) == sel) atomicAdd(&g_hist2[p][(u >> 8) & 0xFFFu], 1u);
        u = __float_as_uint(v[j].z); if ((u >> 20) == sel) atomicAdd(&g_hist2[p][(u >> 8) & 0xFFFu], 1u);
        u = __float_as_uint(v[j].w); if ((u >> 20) == sel) atomicAdd(&g_hist2[p][(u >> 8) & 0xFFFu], 1u);
    }
}

__global__ void __launch_bounds__(256) k_hist3() {
    const float4* __restrict__ src = (const float4*)&g_scr[0][0][0];
    const unsigned idx = blockIdx.x * 256 + threadIdx.x;
    const unsigned stride = 4096u * 256u;
    float4 v[4];
    #pragma unroll
    for (int j = 0; j < 4; j++) v[j] = src[idx + j * stride];
    #pragma unroll
    for (int j = 0; j < 4; j++) {
        const unsigned p = (idx + j * stride) >> 18;
        const unsigned pref = (g_sel1[p] << 12) | g_sel2[p];
        unsigned u;
        u = __float_as_uint(v[j].x); if ((u >> 8) == pref) atomicAdd(&g_hist3[p][u & 0xFFu], 1u);
        u = __float_as_uint(v[j].y); if ((u >> 8) == pref) atomicAdd(&g_hist3[p][u & 0xFFu], 1u);
        u = __float_as_uint(v[j].z); if ((u >> 8) == pref) atomicAdd(&g_hist3[p][u & 0xFFu], 1u);
        u = __float_as_uint(v[j].w); if ((u >> 8) == pref) atomicAdd(&g_hist3[p][u & 0xFFu], 1u);
    }
}

// ---------------------------------------------------------------------------
// K6: masks + loss. out layout: [loss, maskA(8*1M), maskB(8*1M)]
// Last-use read of scratch; streaming stores.
// ---------------------------------------------------------------------------
__global__ void k_mask(float* __restrict__ out) {
    const float4* __restrict__ src = (const float4*)&g_scr[0][0][0];
    const unsigned i = blockIdx.x * blockDim.x + threadIdx.x;
    const unsigned p = i >> 18;
    const float kth = g_kth[p];
    float4 v = __ldcs(src + i);
    size_t off = 1 + ((size_t)i << 2);
    __stcs(out + off + 0, (v.x >= kth) ? 1.0f : 0.0f);
    __stcs(out + off + 1, (v.y >= kth) ? 1.0f : 0.0f);
    __stcs(out + off + 2, (v.z >= kth) ? 1.0f : 0.0f);
    __stcs(out + off + 3, (v.w >= kth) ? 1.0f : 0.0f);
    if (i == 0) out[0] = (float)(g_loss / 8388608.0);
}

// ---------------------------------------------------------------------------
extern "C" void kernel_launch(void* const* d_in, const int* in_sizes, int n_in,
                              void* d_out, int out_size) {
    const float* A   = (const float*)d_in[0];
    const float* Bi  = (const float*)d_in[1];
    const float* F   = (const float*)d_in[2];
    const int*   thr = (const int*)d_in[3];
    float* out = (float*)d_out;

    k_zero<<<64, 256>>>();
    k_sobel<<<dim3(HH / SROWS, BB), 256>>>(A, Bi, F);   // (64, 8)
    k_scan1<<<NPAIR, 512>>>(thr);
    k_hist2<<<4096, 256>>>();
    k_scan2<<<NPAIR, 1024>>>();
    k_hist3<<<4096, 256>>>();
    k_scan3<<<NPAIR, 64>>>();
    k_mask<<<NPAIR * (NPIX / 4) / 256, 256>>>(out);     // 16384 blocks
}